// round 7
// baseline (speedup 1.0000x reference)
#include <cuda_runtime.h>
#include <cuda_bf16.h>

// I_MLP_7206955123212 — B=2^21 independent 10-step tiny-MLP rollouts.
// Scalar FFMA; rc weights streamed from smem (broadcast LDS.128) inside a
// non-unrolled step loop. Occupancy push: launch_bounds(128,6) (<=85 regs,
// 24 warps/SM), shortened live ranges (detached-pred err term consumed
// immediately), vectorized bias loads. Two rows per thread.

__device__ __forceinline__ float tanh_fast(float x) {
    float y; asm("tanh.approx.f32 %0,%1;" : "=f"(y) : "f"(x)); return y;
}
__device__ __forceinline__ float sqrt_fast(float x) {
    float y; asm("sqrt.approx.f32 %0,%1;" : "=f"(y) : "f"(x)); return y;
}

// g_w layout (floats):
//  [0..19]    pred: Wf00,Wf01,Wf10,Wf11, Wh00,Wh01,Wh10,Wh11,
//                   WfS(4), WhS(4), Bf0,Bf1,Bh0,Bh1
//  [20..51]   rc1_w (j*4+k)       [52..59]   rc1_b
//  [60..123]  rc2_w (j*8+k)       [124..131] rc2_b
//  [132..147] rc3_w (r*8+k)       [148..149] rc3_b
__device__ float g_w[160];

__global__ void prep_kernel(const float* __restrict__ fc1_w, const float* __restrict__ fc1_b,
                            const float* __restrict__ fc2_w, const float* __restrict__ fc2_b,
                            const float* __restrict__ rc1_w, const float* __restrict__ rc1_b,
                            const float* __restrict__ rc2_w, const float* __restrict__ rc2_b,
                            const float* __restrict__ rc3_w, const float* __restrict__ rc3_b,
                            const float* __restrict__ hf1_w, const float* __restrict__ hf1_b,
                            const float* __restrict__ hf2_w, const float* __restrict__ hf2_b)
{
    if (threadIdx.x != 0 || blockIdx.x != 0) return;

    // Fuse fc2@fc1 and hf2@hf1 (no activation between) into 2x4 affines.
    float Wf[2][4], Wh[2][4], Bf[2], Bh[2];
    for (int r = 0; r < 2; ++r) {
        for (int k = 0; k < 4; ++k) {
            float af = 0.f, ah = 0.f;
            for (int j = 0; j < 4; ++j) {
                af = fmaf(fc2_w[r * 4 + j], fc1_w[j * 4 + k], af);
                ah = fmaf(hf2_w[r * 4 + j], hf1_w[j * 4 + k], ah);
            }
            Wf[r][k] = af; Wh[r][k] = ah;
        }
        float bf = fc2_b[r], bh = hf2_b[r];
        for (int j = 0; j < 4; ++j) {
            bf = fmaf(fc2_w[r * 4 + j], fc1_b[j], bf);
            bh = fmaf(hf2_w[r * 4 + j], hf1_b[j], bh);
        }
        Bf[r] = bf; Bh[r] = bh;
    }
    g_w[0] = Wf[0][0]; g_w[1] = Wf[0][1]; g_w[2] = Wf[1][0]; g_w[3] = Wf[1][1];
    g_w[4] = Wh[0][0]; g_w[5] = Wh[0][1]; g_w[6] = Wh[1][0]; g_w[7] = Wh[1][1];
    g_w[8]  = Wf[0][2]; g_w[9]  = Wf[0][3]; g_w[10] = Wf[1][2]; g_w[11] = Wf[1][3];
    g_w[12] = Wh[0][2]; g_w[13] = Wh[0][3]; g_w[14] = Wh[1][2]; g_w[15] = Wh[1][3];
    g_w[16] = Bf[0]; g_w[17] = Bf[1]; g_w[18] = Bh[0]; g_w[19] = Bh[1];

    for (int i = 0; i < 32; ++i) g_w[20 + i]  = rc1_w[i];
    for (int i = 0; i < 8;  ++i) g_w[52 + i]  = rc1_b[i];
    for (int i = 0; i < 64; ++i) g_w[60 + i]  = rc2_w[i];
    for (int i = 0; i < 8;  ++i) g_w[124 + i] = rc2_b[i];
    for (int i = 0; i < 16; ++i) g_w[132 + i] = rc3_w[i];
    for (int i = 0; i < 2;  ++i) g_w[148 + i] = rc3_b[i];
}

#define RPT 2

__global__ void __launch_bounds__(128, 6)
rollout_kernel(const float* __restrict__ s_star, const float* __restrict__ s0,
               float* __restrict__ out, int B)
{
    // smem: s_pred[20], then rc blocks in s_w (16B aligned):
    //  rc1w @0, rc1b @32, rc2w @40, rc2b @104, rc3w @112, rc3b @128
    __shared__ float s_pred[20];
    __shared__ __align__(16) float s_w[132];
    for (int i = threadIdx.x; i < 150; i += blockDim.x) {
        if (i < 20) s_pred[i] = g_w[i];
        else        s_w[i - 20] = g_w[i];
    }
    __syncthreads();

    const float4* __restrict__ s4_rc1  = reinterpret_cast<const float4*>(s_w + 0);
    const float4* __restrict__ s4_rc1b = reinterpret_cast<const float4*>(s_w + 32);
    const float4* __restrict__ s4_rc2  = reinterpret_cast<const float4*>(s_w + 40);
    const float4* __restrict__ s4_rc2b = reinterpret_cast<const float4*>(s_w + 104);
    const float4* __restrict__ s4_rc3  = reinterpret_cast<const float4*>(s_w + 112);
    const float2* __restrict__ s2_rc3b = reinterpret_cast<const float2*>(s_w + 128);

    const int base = (blockIdx.x * blockDim.x + threadIdx.x) * RPT;
    if (base >= B) return;

    const float Wf00 = s_pred[0], Wf01 = s_pred[1], Wf10 = s_pred[2], Wf11 = s_pred[3];
    const float Wh00 = s_pred[4], Wh01 = s_pred[5], Wh10 = s_pred[6], Wh11 = s_pred[7];

    float sx[RPT], sy[RPT], ssx[RPT], ssy[RPT], err[RPT];
    float Cf0[RPT], Cf1[RPT], Ch0[RPT], Ch1[RPT];
    #pragma unroll
    for (int r = 0; r < RPT; ++r) {
        const int i = (base + r < B) ? base + r : B - 1;
        const float2 ssv = reinterpret_cast<const float2*>(s_star)[i];
        const float2 s0v = reinterpret_cast<const float2*>(s0)[i];
        ssx[r] = ssv.x; ssy[r] = ssv.y;
        sx[r] = s0v.x;  sy[r] = s0v.y;  err[r] = 0.f;
        Cf0[r] = fmaf(s_pred[8],  ssv.x, fmaf(s_pred[9],  ssv.y, s_pred[16]));
        Cf1[r] = fmaf(s_pred[10], ssv.x, fmaf(s_pred[11], ssv.y, s_pred[17]));
        Ch0[r] = fmaf(s_pred[12], ssv.x, fmaf(s_pred[13], ssv.y, s_pred[18]));
        Ch1[r] = fmaf(s_pred[14], ssv.x, fmaf(s_pred[15], ssv.y, s_pred[19]));
    }

    // Step loop NOT unrolled: keeps smem weight loads inside the loop body.
    #pragma unroll 1
    for (int t = 0; t < 10; ++t) {
        float ah0[RPT], ah1[RPT];
        #pragma unroll
        for (int r = 0; r < RPT; ++r) {
            // prediction nets (register weights)
            ah0[r] = tanh_fast(fmaf(Wf00, sx[r], fmaf(Wf01, sy[r], Cf0[r])));
            ah1[r] = tanh_fast(fmaf(Wf10, sx[r], fmaf(Wf11, sy[r], Cf1[r])));
            const float ag0 = tanh_fast(fmaf(Wh00, sx[r], fmaf(Wh01, sy[r], Ch0[r])));
            const float ag1 = tanh_fast(fmaf(Wh10, sx[r], fmaf(Wh11, sy[r], Ch1[r])));
            // detached-pred err term consumed immediately (kills ag live range)
            const float d0 = ah0[r] - ag0, d1 = ah1[r] - ag1;
            err[r] += sqrt_fast(fmaf(d0, d0, d1 * d1));
        }

        // rc1: [s, ah] -> 8  (weights broadcast from smem, shared by both rows)
        float h1[RPT][8];
        {
            const float4 b1a = s4_rc1b[0], b1b = s4_rc1b[1];
            const float bb[8] = {b1a.x, b1a.y, b1a.z, b1a.w, b1b.x, b1b.y, b1b.z, b1b.w};
            #pragma unroll
            for (int j = 0; j < 8; ++j) {
                const float4 w = s4_rc1[j];
                #pragma unroll
                for (int r = 0; r < RPT; ++r)
                    h1[r][j] = tanh_fast(fmaf(w.x, sx[r],
                                         fmaf(w.y, sy[r],
                                         fmaf(w.z, ah0[r],
                                         fmaf(w.w, ah1[r], bb[j])))));
            }
        }

        // ah-only err terms now (kills ah live range before rc2)
        #pragma unroll
        for (int r = 0; r < RPT; ++r) {
            err[r] += tanh_fast(ah0[r]) + tanh_fast(ah1[r]);
            err[r] += sqrt_fast(fmaf(ah0[r], ah0[r], ah1[r] * ah1[r]));
        }

        // rc2: 8 -> 8
        float h2[RPT][8];
        {
            const float4 b2a = s4_rc2b[0], b2b = s4_rc2b[1];
            const float bb[8] = {b2a.x, b2a.y, b2a.z, b2a.w, b2b.x, b2b.y, b2b.z, b2b.w};
            #pragma unroll
            for (int j = 0; j < 8; ++j) {
                const float4 wa = s4_rc2[2 * j];
                const float4 wb = s4_rc2[2 * j + 1];
                #pragma unroll
                for (int r = 0; r < RPT; ++r) {
                    float a = fmaf(wa.x, h1[r][0], fmaf(wa.y, h1[r][1],
                              fmaf(wa.z, h1[r][2], fmaf(wa.w, h1[r][3], bb[j]))));
                    a = fmaf(wb.x, h1[r][4], fmaf(wb.y, h1[r][5],
                        fmaf(wb.z, h1[r][6], fmaf(wb.w, h1[r][7], a))));
                    h2[r][j] = tanh_fast(a);
                }
            }
        }

        // rc3: 8 -> 2, state update, tracking error
        {
            const float4 wa0 = s4_rc3[0], wa1 = s4_rc3[1];
            const float4 wb0 = s4_rc3[2], wb1 = s4_rc3[3];
            const float2 b3 = s2_rc3b[0];
            #pragma unroll
            for (int r = 0; r < RPT; ++r) {
                float ar0 = fmaf(wa0.x, h2[r][0], fmaf(wa0.y, h2[r][1],
                            fmaf(wa0.z, h2[r][2], fmaf(wa0.w, h2[r][3], b3.x))));
                ar0 = fmaf(wa1.x, h2[r][4], fmaf(wa1.y, h2[r][5],
                      fmaf(wa1.z, h2[r][6], fmaf(wa1.w, h2[r][7], ar0))));
                float ar1 = fmaf(wb0.x, h2[r][0], fmaf(wb0.y, h2[r][1],
                            fmaf(wb0.z, h2[r][2], fmaf(wb0.w, h2[r][3], b3.y))));
                ar1 = fmaf(wb1.x, h2[r][4], fmaf(wb1.y, h2[r][5],
                      fmaf(wb1.z, h2[r][6], fmaf(wb1.w, h2[r][7], ar1))));
                sx[r] = fmaf(0.1f, ar0, sx[r]);
                sy[r] = fmaf(0.1f, ar1, sy[r]);

                const float dx = sx[r] - ssx[r], dy = sy[r] - ssy[r];
                err[r] += fmaf(dx, dx, dy * dy);
            }
        }
    }

    #pragma unroll
    for (int r = 0; r < RPT; ++r)
        if (base + r < B) out[base + r] = err[r];
}

extern "C" void kernel_launch(void* const* d_in, const int* in_sizes, int n_in,
                              void* d_out, int out_size)
{
    const float* s_star = (const float*)d_in[0];
    const float* s0     = (const float*)d_in[1];
    const float* fc1_w  = (const float*)d_in[2];
    const float* fc1_b  = (const float*)d_in[3];
    const float* fc2_w  = (const float*)d_in[4];
    const float* fc2_b  = (const float*)d_in[5];
    const float* rc1_w  = (const float*)d_in[6];
    const float* rc1_b  = (const float*)d_in[7];
    const float* rc2_w  = (const float*)d_in[8];
    const float* rc2_b  = (const float*)d_in[9];
    const float* rc3_w  = (const float*)d_in[10];
    const float* rc3_b  = (const float*)d_in[11];
    const float* hf1_w  = (const float*)d_in[12];
    const float* hf1_b  = (const float*)d_in[13];
    const float* hf2_w  = (const float*)d_in[14];
    const float* hf2_b  = (const float*)d_in[15];
    float* out = (float*)d_out;

    const int B = out_size;

    prep_kernel<<<1, 1>>>(fc1_w, fc1_b, fc2_w, fc2_b,
                          rc1_w, rc1_b, rc2_w, rc2_b, rc3_w, rc3_b,
                          hf1_w, hf1_b, hf2_w, hf2_b);

    const int threads = 128;
    const int rows_per_block = threads * RPT;
    const int blocks = (B + rows_per_block - 1) / rows_per_block;
    rollout_kernel<<<blocks, threads>>>(s_star, s0, out, B);
}

// round 8
// speedup vs baseline: 1.0402x; 1.0402x over previous
#include <cuda_runtime.h>
#include <cuda_bf16.h>

// I_MLP_7206955123212 — B=2^21 independent 10-step tiny-MLP rollouts.
// R5 structure (scalar bias LDS, no spills) + register-demand reduction:
// per-row loop-invariant constants (Cf/Ch, s_star) live in per-thread smem
// SoA slots, re-read each step via volatile LDS so ptxas can't hoist them.
// Goal: true demand <=85 regs -> 6 blocks/SM (24 warps) with ZERO spill.

__device__ __forceinline__ float tanh_fast(float x) {
    float y; asm("tanh.approx.f32 %0,%1;" : "=f"(y) : "f"(x)); return y;
}
__device__ __forceinline__ float sqrt_fast(float x) {
    float y; asm("sqrt.approx.f32 %0,%1;" : "=f"(y) : "f"(x)); return y;
}

// g_w layout (floats):
//  [0..19]    pred: Wf00,Wf01,Wf10,Wf11, Wh00,Wh01,Wh10,Wh11,
//                   WfS(4), WhS(4), Bf0,Bf1,Bh0,Bh1
//  [20..51]   rc1_w (j*4+k)       [52..59]   rc1_b
//  [60..123]  rc2_w (j*8+k)       [124..131] rc2_b
//  [132..147] rc3_w (r*8+k)       [148..149] rc3_b
__device__ float g_w[160];

__global__ void prep_kernel(const float* __restrict__ fc1_w, const float* __restrict__ fc1_b,
                            const float* __restrict__ fc2_w, const float* __restrict__ fc2_b,
                            const float* __restrict__ rc1_w, const float* __restrict__ rc1_b,
                            const float* __restrict__ rc2_w, const float* __restrict__ rc2_b,
                            const float* __restrict__ rc3_w, const float* __restrict__ rc3_b,
                            const float* __restrict__ hf1_w, const float* __restrict__ hf1_b,
                            const float* __restrict__ hf2_w, const float* __restrict__ hf2_b)
{
    if (threadIdx.x != 0 || blockIdx.x != 0) return;

    // Fuse fc2@fc1 and hf2@hf1 (no activation between) into 2x4 affines.
    float Wf[2][4], Wh[2][4], Bf[2], Bh[2];
    for (int r = 0; r < 2; ++r) {
        for (int k = 0; k < 4; ++k) {
            float af = 0.f, ah = 0.f;
            for (int j = 0; j < 4; ++j) {
                af = fmaf(fc2_w[r * 4 + j], fc1_w[j * 4 + k], af);
                ah = fmaf(hf2_w[r * 4 + j], hf1_w[j * 4 + k], ah);
            }
            Wf[r][k] = af; Wh[r][k] = ah;
        }
        float bf = fc2_b[r], bh = hf2_b[r];
        for (int j = 0; j < 4; ++j) {
            bf = fmaf(fc2_w[r * 4 + j], fc1_b[j], bf);
            bh = fmaf(hf2_w[r * 4 + j], hf1_b[j], bh);
        }
        Bf[r] = bf; Bh[r] = bh;
    }
    g_w[0] = Wf[0][0]; g_w[1] = Wf[0][1]; g_w[2] = Wf[1][0]; g_w[3] = Wf[1][1];
    g_w[4] = Wh[0][0]; g_w[5] = Wh[0][1]; g_w[6] = Wh[1][0]; g_w[7] = Wh[1][1];
    g_w[8]  = Wf[0][2]; g_w[9]  = Wf[0][3]; g_w[10] = Wf[1][2]; g_w[11] = Wf[1][3];
    g_w[12] = Wh[0][2]; g_w[13] = Wh[0][3]; g_w[14] = Wh[1][2]; g_w[15] = Wh[1][3];
    g_w[16] = Bf[0]; g_w[17] = Bf[1]; g_w[18] = Bh[0]; g_w[19] = Bh[1];

    for (int i = 0; i < 32; ++i) g_w[20 + i]  = rc1_w[i];
    for (int i = 0; i < 8;  ++i) g_w[52 + i]  = rc1_b[i];
    for (int i = 0; i < 64; ++i) g_w[60 + i]  = rc2_w[i];
    for (int i = 0; i < 8;  ++i) g_w[124 + i] = rc2_b[i];
    for (int i = 0; i < 16; ++i) g_w[132 + i] = rc3_w[i];
    for (int i = 0; i < 2;  ++i) g_w[148 + i] = rc3_b[i];
}

#define RPT 2

__global__ void __launch_bounds__(128, 6)
rollout_kernel(const float* __restrict__ s_star, const float* __restrict__ s0,
               float* __restrict__ out, int B)
{
    // Weights (shared by all threads): rc1w @0, rc1b @32, rc2w @40, rc2b @104,
    // rc3w @112, rc3b @128. Pred s-half weights in s_pred[0..7].
    __shared__ float s_pred[8];
    __shared__ __align__(16) float s_w[132];
    // Per-thread loop-invariant constants, SoA [slot][thread] (conflict-free):
    //  slots 0..3: Cf0,Cf1,Ch0,Ch1 (row 0); 4..7: same (row 1);
    //  slots 8..9: ssx,ssy (row 0);  10..11: (row 1)
    __shared__ float sC[12][128];

    const int tid = threadIdx.x;
    for (int i = tid; i < 140; i += blockDim.x) {
        if (i < 8) s_pred[i] = g_w[i];
        else       s_w[i - 8] = g_w[i + 12];
    }

    const int base = (blockIdx.x * blockDim.x + tid) * RPT;

    float sx[RPT], sy[RPT], err[RPT];
    {
        // Fold the s_star half of the fused prediction affines per-row, park in smem.
        #pragma unroll
        for (int r = 0; r < RPT; ++r) {
            const int i = (base + r < B) ? base + r : B - 1;
            const float2 ssv = reinterpret_cast<const float2*>(s_star)[i];
            const float2 s0v = reinterpret_cast<const float2*>(s0)[i];
            sx[r] = s0v.x; sy[r] = s0v.y; err[r] = 0.f;
            sC[r * 4 + 0][tid] = fmaf(g_w[8],  ssv.x, fmaf(g_w[9],  ssv.y, g_w[16]));
            sC[r * 4 + 1][tid] = fmaf(g_w[10], ssv.x, fmaf(g_w[11], ssv.y, g_w[17]));
            sC[r * 4 + 2][tid] = fmaf(g_w[12], ssv.x, fmaf(g_w[13], ssv.y, g_w[18]));
            sC[r * 4 + 3][tid] = fmaf(g_w[14], ssv.x, fmaf(g_w[15], ssv.y, g_w[19]));
            sC[8 + r * 2][tid] = ssv.x;
            sC[9 + r * 2][tid] = ssv.y;
        }
    }
    __syncthreads();

    const float4* __restrict__ s4_rc1 = reinterpret_cast<const float4*>(s_w + 0);
    const float*  __restrict__ s_rc1b = s_w + 32;
    const float4* __restrict__ s4_rc2 = reinterpret_cast<const float4*>(s_w + 40);
    const float*  __restrict__ s_rc2b = s_w + 104;
    const float4* __restrict__ s4_rc3 = reinterpret_cast<const float4*>(s_w + 112);
    const float*  __restrict__ s_rc3b = s_w + 128;
    // volatile view stops ptxas from hoisting these loop-invariant LDS into
    // long-lived registers (that hoist is exactly what blew the reg budget).
    volatile const float* vC = &sC[0][0];

    const float Wf00 = s_pred[0], Wf01 = s_pred[1], Wf10 = s_pred[2], Wf11 = s_pred[3];
    const float Wh00 = s_pred[4], Wh01 = s_pred[5], Wh10 = s_pred[6], Wh11 = s_pred[7];

    if (base >= B) return;

    // Step loop NOT unrolled: keeps smem weight loads inside the loop body.
    #pragma unroll 1
    for (int t = 0; t < 10; ++t) {
        float ah0[RPT], ah1[RPT];
        #pragma unroll
        for (int r = 0; r < RPT; ++r) {
            const float cf0 = vC[(r * 4 + 0) * 128 + tid];
            const float cf1 = vC[(r * 4 + 1) * 128 + tid];
            const float ch0 = vC[(r * 4 + 2) * 128 + tid];
            const float ch1 = vC[(r * 4 + 3) * 128 + tid];
            ah0[r] = tanh_fast(fmaf(Wf00, sx[r], fmaf(Wf01, sy[r], cf0)));
            ah1[r] = tanh_fast(fmaf(Wf10, sx[r], fmaf(Wf11, sy[r], cf1)));
            const float ag0 = tanh_fast(fmaf(Wh00, sx[r], fmaf(Wh01, sy[r], ch0)));
            const float ag1 = tanh_fast(fmaf(Wh10, sx[r], fmaf(Wh11, sy[r], ch1)));
            // detached-pred err term consumed immediately (kills ag live range)
            const float d0 = ah0[r] - ag0, d1 = ah1[r] - ag1;
            float e = err[r];
            e += sqrt_fast(fmaf(d0, d0, d1 * d1));
            // ah-only err terms now too (ah stays live only through rc1)
            e += tanh_fast(ah0[r]) + tanh_fast(ah1[r]);
            e += sqrt_fast(fmaf(ah0[r], ah0[r], ah1[r] * ah1[r]));
            err[r] = e;
        }

        // rc1: [s, ah] -> 8  (weights broadcast from smem, shared by both rows)
        float h1[RPT][8];
        #pragma unroll
        for (int j = 0; j < 8; ++j) {
            const float4 w = s4_rc1[j];
            const float  b = s_rc1b[j];
            #pragma unroll
            for (int r = 0; r < RPT; ++r)
                h1[r][j] = tanh_fast(fmaf(w.x, sx[r],
                                     fmaf(w.y, sy[r],
                                     fmaf(w.z, ah0[r],
                                     fmaf(w.w, ah1[r], b)))));
        }

        // rc2: 8 -> 8
        float h2[RPT][8];
        #pragma unroll
        for (int j = 0; j < 8; ++j) {
            const float4 wa = s4_rc2[2 * j];
            const float4 wb = s4_rc2[2 * j + 1];
            const float  b  = s_rc2b[j];
            #pragma unroll
            for (int r = 0; r < RPT; ++r) {
                float a = fmaf(wa.x, h1[r][0], fmaf(wa.y, h1[r][1],
                          fmaf(wa.z, h1[r][2], fmaf(wa.w, h1[r][3], b))));
                a = fmaf(wb.x, h1[r][4], fmaf(wb.y, h1[r][5],
                    fmaf(wb.z, h1[r][6], fmaf(wb.w, h1[r][7], a))));
                h2[r][j] = tanh_fast(a);
            }
        }

        // rc3: 8 -> 2, state update, tracking error
        {
            const float4 wa0 = s4_rc3[0], wa1 = s4_rc3[1];
            const float4 wb0 = s4_rc3[2], wb1 = s4_rc3[3];
            const float  b30 = s_rc3b[0], b31 = s_rc3b[1];
            #pragma unroll
            for (int r = 0; r < RPT; ++r) {
                float ar0 = fmaf(wa0.x, h2[r][0], fmaf(wa0.y, h2[r][1],
                            fmaf(wa0.z, h2[r][2], fmaf(wa0.w, h2[r][3], b30))));
                ar0 = fmaf(wa1.x, h2[r][4], fmaf(wa1.y, h2[r][5],
                      fmaf(wa1.z, h2[r][6], fmaf(wa1.w, h2[r][7], ar0))));
                float ar1 = fmaf(wb0.x, h2[r][0], fmaf(wb0.y, h2[r][1],
                            fmaf(wb0.z, h2[r][2], fmaf(wb0.w, h2[r][3], b31))));
                ar1 = fmaf(wb1.x, h2[r][4], fmaf(wb1.y, h2[r][5],
                      fmaf(wb1.z, h2[r][6], fmaf(wb1.w, h2[r][7], ar1))));
                sx[r] = fmaf(0.1f, ar0, sx[r]);
                sy[r] = fmaf(0.1f, ar1, sy[r]);

                const float dx = sx[r] - vC[(8 + r * 2) * 128 + tid];
                const float dy = sy[r] - vC[(9 + r * 2) * 128 + tid];
                err[r] += fmaf(dx, dx, dy * dy);
            }
        }
    }

    #pragma unroll
    for (int r = 0; r < RPT; ++r)
        if (base + r < B) out[base + r] = err[r];
}

extern "C" void kernel_launch(void* const* d_in, const int* in_sizes, int n_in,
                              void* d_out, int out_size)
{
    const float* s_star = (const float*)d_in[0];
    const float* s0     = (const float*)d_in[1];
    const float* fc1_w  = (const float*)d_in[2];
    const float* fc1_b  = (const float*)d_in[3];
    const float* fc2_w  = (const float*)d_in[4];
    const float* fc2_b  = (const float*)d_in[5];
    const float* rc1_w  = (const float*)d_in[6];
    const float* rc1_b  = (const float*)d_in[7];
    const float* rc2_w  = (const float*)d_in[8];
    const float* rc2_b  = (const float*)d_in[9];
    const float* rc3_w  = (const float*)d_in[10];
    const float* rc3_b  = (const float*)d_in[11];
    const float* hf1_w  = (const float*)d_in[12];
    const float* hf1_b  = (const float*)d_in[13];
    const float* hf2_w  = (const float*)d_in[14];
    const float* hf2_b  = (const float*)d_in[15];
    float* out = (float*)d_out;

    const int B = out_size;

    prep_kernel<<<1, 1>>>(fc1_w, fc1_b, fc2_w, fc2_b,
                          rc1_w, rc1_b, rc2_w, rc2_b, rc3_w, rc3_b,
                          hf1_w, hf1_b, hf2_w, hf2_b);

    const int threads = 128;
    const int rows_per_block = threads * RPT;
    const int blocks = (B + rows_per_block - 1) / rows_per_block;
    rollout_kernel<<<blocks, threads>>>(s_star, s0, out, B);
}

// round 10
// speedup vs baseline: 1.2078x; 1.1611x over previous
#include <cuda_runtime.h>
#include <cuda_bf16.h>

// I_MLP_7206955123212 — B=2^21 independent 10-step tiny-MLP rollouts.
// R5 structure (known-good: scalar bias LDS, zero spill) with RPT=3:
// 3 independent rollout chains per warp to attack the latency-limited
// issue gap (occupancy is reg-capped at ~20 warps; ILP is the free axis).

__device__ __forceinline__ float tanh_fast(float x) {
    float y; asm("tanh.approx.f32 %0,%1;" : "=f"(y) : "f"(x)); return y;
}
__device__ __forceinline__ float sqrt_fast(float x) {
    float y; asm("sqrt.approx.f32 %0,%1;" : "=f"(y) : "f"(x)); return y;
}

// g_w layout (floats):
//  [0..19]    pred: Wf00,Wf01,Wf10,Wf11, Wh00,Wh01,Wh10,Wh11,
//                   WfS(4), WhS(4), Bf0,Bf1,Bh0,Bh1
//  [20..51]   rc1_w (j*4+k)       [52..59]   rc1_b
//  [60..123]  rc2_w (j*8+k)       [124..131] rc2_b
//  [132..147] rc3_w (r*8+k)       [148..149] rc3_b
__device__ float g_w[160];

__global__ void prep_kernel(const float* __restrict__ fc1_w, const float* __restrict__ fc1_b,
                            const float* __restrict__ fc2_w, const float* __restrict__ fc2_b,
                            const float* __restrict__ rc1_w, const float* __restrict__ rc1_b,
                            const float* __restrict__ rc2_w, const float* __restrict__ rc2_b,
                            const float* __restrict__ rc3_w, const float* __restrict__ rc3_b,
                            const float* __restrict__ hf1_w, const float* __restrict__ hf1_b,
                            const float* __restrict__ hf2_w, const float* __restrict__ hf2_b)
{
    if (threadIdx.x != 0 || blockIdx.x != 0) return;

    // Fuse fc2@fc1 and hf2@hf1 (no activation between) into 2x4 affines.
    float Wf[2][4], Wh[2][4], Bf[2], Bh[2];
    for (int r = 0; r < 2; ++r) {
        for (int k = 0; k < 4; ++k) {
            float af = 0.f, ah = 0.f;
            for (int j = 0; j < 4; ++j) {
                af = fmaf(fc2_w[r * 4 + j], fc1_w[j * 4 + k], af);
                ah = fmaf(hf2_w[r * 4 + j], hf1_w[j * 4 + k], ah);
            }
            Wf[r][k] = af; Wh[r][k] = ah;
        }
        float bf = fc2_b[r], bh = hf2_b[r];
        for (int j = 0; j < 4; ++j) {
            bf = fmaf(fc2_w[r * 4 + j], fc1_b[j], bf);
            bh = fmaf(hf2_w[r * 4 + j], hf1_b[j], bh);
        }
        Bf[r] = bf; Bh[r] = bh;
    }
    g_w[0] = Wf[0][0]; g_w[1] = Wf[0][1]; g_w[2] = Wf[1][0]; g_w[3] = Wf[1][1];
    g_w[4] = Wh[0][0]; g_w[5] = Wh[0][1]; g_w[6] = Wh[1][0]; g_w[7] = Wh[1][1];
    g_w[8]  = Wf[0][2]; g_w[9]  = Wf[0][3]; g_w[10] = Wf[1][2]; g_w[11] = Wf[1][3];
    g_w[12] = Wh[0][2]; g_w[13] = Wh[0][3]; g_w[14] = Wh[1][2]; g_w[15] = Wh[1][3];
    g_w[16] = Bf[0]; g_w[17] = Bf[1]; g_w[18] = Bh[0]; g_w[19] = Bh[1];

    for (int i = 0; i < 32; ++i) g_w[20 + i]  = rc1_w[i];
    for (int i = 0; i < 8;  ++i) g_w[52 + i]  = rc1_b[i];
    for (int i = 0; i < 64; ++i) g_w[60 + i]  = rc2_w[i];
    for (int i = 0; i < 8;  ++i) g_w[124 + i] = rc2_b[i];
    for (int i = 0; i < 16; ++i) g_w[132 + i] = rc3_w[i];
    for (int i = 0; i < 2;  ++i) g_w[148 + i] = rc3_b[i];
}

#define RPT 3

__global__ void __launch_bounds__(128, 4)
rollout_kernel(const float* __restrict__ s_star, const float* __restrict__ s0,
               float* __restrict__ out, int B)
{
    // smem: s_pred[20], then rc blocks in s_w (16B aligned):
    //  rc1w @0, rc1b @32, rc2w @40, rc2b @104, rc3w @112, rc3b @128
    __shared__ float s_pred[20];
    __shared__ __align__(16) float s_w[132];
    for (int i = threadIdx.x; i < 150; i += blockDim.x) {
        if (i < 20) s_pred[i] = g_w[i];
        else        s_w[i - 20] = g_w[i];
    }
    __syncthreads();

    const float4* __restrict__ s4_rc1 = reinterpret_cast<const float4*>(s_w + 0);
    const float*  __restrict__ s_rc1b = s_w + 32;
    const float4* __restrict__ s4_rc2 = reinterpret_cast<const float4*>(s_w + 40);
    const float*  __restrict__ s_rc2b = s_w + 104;
    const float4* __restrict__ s4_rc3 = reinterpret_cast<const float4*>(s_w + 112);
    const float*  __restrict__ s_rc3b = s_w + 128;

    const int base = (blockIdx.x * blockDim.x + threadIdx.x) * RPT;
    if (base >= B) return;

    const float Wf00 = s_pred[0], Wf01 = s_pred[1], Wf10 = s_pred[2], Wf11 = s_pred[3];
    const float Wh00 = s_pred[4], Wh01 = s_pred[5], Wh10 = s_pred[6], Wh11 = s_pred[7];

    float sx[RPT], sy[RPT], ssx[RPT], ssy[RPT], err[RPT];
    float Cf0[RPT], Cf1[RPT], Ch0[RPT], Ch1[RPT];
    #pragma unroll
    for (int r = 0; r < RPT; ++r) {
        const int i = (base + r < B) ? base + r : B - 1;
        const float2 ssv = reinterpret_cast<const float2*>(s_star)[i];
        const float2 s0v = reinterpret_cast<const float2*>(s0)[i];
        ssx[r] = ssv.x; ssy[r] = ssv.y;
        sx[r] = s0v.x;  sy[r] = s0v.y;  err[r] = 0.f;
        Cf0[r] = fmaf(s_pred[8],  ssv.x, fmaf(s_pred[9],  ssv.y, s_pred[16]));
        Cf1[r] = fmaf(s_pred[10], ssv.x, fmaf(s_pred[11], ssv.y, s_pred[17]));
        Ch0[r] = fmaf(s_pred[12], ssv.x, fmaf(s_pred[13], ssv.y, s_pred[18]));
        Ch1[r] = fmaf(s_pred[14], ssv.x, fmaf(s_pred[15], ssv.y, s_pred[19]));
    }

    // Step loop NOT unrolled: keeps smem weight loads inside the loop body
    // (hoisting them into long-lived registers is what causes spills).
    #pragma unroll 1
    for (int t = 0; t < 10; ++t) {
        float ah0[RPT], ah1[RPT];
        #pragma unroll
        for (int r = 0; r < RPT; ++r) {
            // prediction nets (register weights)
            ah0[r] = tanh_fast(fmaf(Wf00, sx[r], fmaf(Wf01, sy[r], Cf0[r])));
            ah1[r] = tanh_fast(fmaf(Wf10, sx[r], fmaf(Wf11, sy[r], Cf1[r])));
            const float ag0 = tanh_fast(fmaf(Wh00, sx[r], fmaf(Wh01, sy[r], Ch0[r])));
            const float ag1 = tanh_fast(fmaf(Wh10, sx[r], fmaf(Wh11, sy[r], Ch1[r])));
            // detached-pred err term consumed immediately (kills ag live range)
            const float d0 = ah0[r] - ag0, d1 = ah1[r] - ag1;
            float e = err[r];
            e += sqrt_fast(fmaf(d0, d0, d1 * d1));
            // ah-only err terms here too (ah stays live only through rc1)
            e += tanh_fast(ah0[r]) + tanh_fast(ah1[r]);
            e += sqrt_fast(fmaf(ah0[r], ah0[r], ah1[r] * ah1[r]));
            err[r] = e;
        }

        // rc1: [s, ah] -> 8  (weights broadcast from smem, shared by all rows)
        float h1[RPT][8];
        #pragma unroll
        for (int j = 0; j < 8; ++j) {
            const float4 w = s4_rc1[j];
            const float  b = s_rc1b[j];
            #pragma unroll
            for (int r = 0; r < RPT; ++r)
                h1[r][j] = tanh_fast(fmaf(w.x, sx[r],
                                     fmaf(w.y, sy[r],
                                     fmaf(w.z, ah0[r],
                                     fmaf(w.w, ah1[r], b)))));
        }

        // rc2: 8 -> 8
        float h2[RPT][8];
        #pragma unroll
        for (int j = 0; j < 8; ++j) {
            const float4 wa = s4_rc2[2 * j];
            const float4 wb = s4_rc2[2 * j + 1];
            const float  b  = s_rc2b[j];
            #pragma unroll
            for (int r = 0; r < RPT; ++r) {
                float a = fmaf(wa.x, h1[r][0], fmaf(wa.y, h1[r][1],
                          fmaf(wa.z, h1[r][2], fmaf(wa.w, h1[r][3], b))));
                a = fmaf(wb.x, h1[r][4], fmaf(wb.y, h1[r][5],
                    fmaf(wb.z, h1[r][6], fmaf(wb.w, h1[r][7], a))));
                h2[r][j] = tanh_fast(a);
            }
        }

        // rc3: 8 -> 2, state update, tracking error
        {
            const float4 wa0 = s4_rc3[0], wa1 = s4_rc3[1];
            const float4 wb0 = s4_rc3[2], wb1 = s4_rc3[3];
            const float  b30 = s_rc3b[0], b31 = s_rc3b[1];
            #pragma unroll
            for (int r = 0; r < RPT; ++r) {
                float ar0 = fmaf(wa0.x, h2[r][0], fmaf(wa0.y, h2[r][1],
                            fmaf(wa0.z, h2[r][2], fmaf(wa0.w, h2[r][3], b30))));
                ar0 = fmaf(wa1.x, h2[r][4], fmaf(wa1.y, h2[r][5],
                      fmaf(wa1.z, h2[r][6], fmaf(wa1.w, h2[r][7], ar0))));
                float ar1 = fmaf(wb0.x, h2[r][0], fmaf(wb0.y, h2[r][1],
                            fmaf(wb0.z, h2[r][2], fmaf(wb0.w, h2[r][3], b31))));
                ar1 = fmaf(wb1.x, h2[r][4], fmaf(wb1.y, h2[r][5],
                      fmaf(wb1.z, h2[r][6], fmaf(wb1.w, h2[r][7], ar1))));
                sx[r] = fmaf(0.1f, ar0, sx[r]);
                sy[r] = fmaf(0.1f, ar1, sy[r]);

                const float dx = sx[r] - ssx[r], dy = sy[r] - ssy[r];
                err[r] += fmaf(dx, dx, dy * dy);
            }
        }
    }

    #pragma unroll
    for (int r = 0; r < RPT; ++r)
        if (base + r < B) out[base + r] = err[r];
}

extern "C" void kernel_launch(void* const* d_in, const int* in_sizes, int n_in,
                              void* d_out, int out_size)
{
    const float* s_star = (const float*)d_in[0];
    const float* s0     = (const float*)d_in[1];
    const float* fc1_w  = (const float*)d_in[2];
    const float* fc1_b  = (const float*)d_in[3];
    const float* fc2_w  = (const float*)d_in[4];
    const float* fc2_b  = (const float*)d_in[5];
    const float* rc1_w  = (const float*)d_in[6];
    const float* rc1_b  = (const float*)d_in[7];
    const float* rc2_w  = (const float*)d_in[8];
    const float* rc2_b  = (const float*)d_in[9];
    const float* rc3_w  = (const float*)d_in[10];
    const float* rc3_b  = (const float*)d_in[11];
    const float* hf1_w  = (const float*)d_in[12];
    const float* hf1_b  = (const float*)d_in[13];
    const float* hf2_w  = (const float*)d_in[14];
    const float* hf2_b  = (const float*)d_in[15];
    float* out = (float*)d_out;

    const int B = out_size;

    prep_kernel<<<1, 1>>>(fc1_w, fc1_b, fc2_w, fc2_b,
                          rc1_w, rc1_b, rc2_w, rc2_b, rc3_w, rc3_b,
                          hf1_w, hf1_b, hf2_w, hf2_b);

    const int threads = 128;
    const int rows_per_block = threads * RPT;
    const int blocks = (B + rows_per_block - 1) / rows_per_block;
    rollout_kernel<<<blocks, threads>>>(s_star, s0, out, B);
}